// round 15
// baseline (speedup 1.0000x reference)
#include <cuda_runtime.h>
#include <cstdint>

#define Bsz 4
#define Ssz 80
#define Psz 6500
#define Ff  128
#define Hh  128
#define TP  128
#define HSTR 68         // padded stride for h tile (conflict-free mma B-frag loads)
#define NSLICE 4
#define TILES_PER_SLICE 13   // 4*13*128 = 6656 >= 6500

// ---------------- scratch (device globals; no allocations allowed) ----------------
__device__ float g_emb4[NSLICE][Bsz * Ssz * Ff];  // per-slice partial max
__device__ float g_xg[2 * Bsz * Ssz * 4 * Hh];    // (dir,b,t,512) input-gate preacts
__device__ float g_hfin[2 * Bsz * Hh];            // final hidden per (dir,b)

// ---------------- helpers ----------------
__device__ __forceinline__ unsigned f2tf32(float x) {
    unsigned r;
    asm("cvt.rna.tf32.f32 %0, %1;" : "=r"(r) : "f"(x));
    return r;
}

__device__ __forceinline__ void mma_tf32(float* c, const unsigned* a, unsigned b0, unsigned b1) {
    asm volatile(
        "mma.sync.aligned.m16n8k8.row.col.f32.tf32.tf32.f32 "
        "{%0,%1,%2,%3}, {%4,%5,%6,%7}, {%8,%9}, {%0,%1,%2,%3};"
        : "+f"(c[0]), "+f"(c[1]), "+f"(c[2]), "+f"(c[3])
        : "r"(a[0]), "r"(a[1]), "r"(a[2]), "r"(a[3]), "r"(b0), "r"(b1));
}

// ---------------- kernel A: per-point MLP + masked max-pool ------------------------
// grid = 4 blocks (point slices) per (b,s) row, 512 threads, 13 tiles of 128 points.
// GEMM1 (2->64) fp32 FFMA; GEMM2 (64->128) via m16n8k8 tf32 mma, fp32 accum.
// Warp layout: 16 warps = (mi 0..7: 16-feature tile) x (pjj 0..1: 64-point group).
__global__ void __launch_bounds__(512, 1) pointnet_kernel(
    const float* __restrict__ slices, const float* __restrict__ pmask,
    const float* __restrict__ W1, const float* __restrict__ b1,
    const float* __restrict__ W2, const float* __restrict__ b2)
{
    __shared__ float sW1[64][2];
    __shared__ float sb1[64];
    __shared__ float sxy[2][TP * 2];    // double-buffered point staging
    __shared__ float smask[2][TP];      // double-buffered mask staging
    __shared__ float sh[TP * HSTR];     // tf32 bit-patterns stored as float
    __shared__ float smax[Ff];

    const int tid   = threadIdx.x;
    const int bs    = blockIdx.x >> 2;
    const int slice = blockIdx.x & 3;
    const int tile0 = slice * TILES_PER_SLICE;
    const int tile1 = tile0 + TILES_PER_SLICE;

    if (tid < 64) { sW1[tid][0] = W1[tid * 2]; sW1[tid][1] = W1[tid * 2 + 1]; sb1[tid] = b1[tid]; }
    if (tid < Ff) smax[tid] = 0.f;

    const int w    = tid >> 5;
    const int lane = tid & 31;
    const int g    = lane >> 2;   // groupID
    const int tg   = lane & 3;    // threadID in group
    const int mi   = w >> 1;      // feature tile 0..7
    const int pjj  = w & 1;       // point half within tile
    const int f0 = mi * 16 + g, f1 = f0 + 8;
    const float b2f0 = b2[f0], b2f1 = b2[f1];

    // A fragments (W2 as A operand, M=features) -- constant across all tiles
    unsigned afr[8][4];
#pragma unroll
    for (int ks = 0; ks < 8; ks++) {
        int c0 = ks * 8 + tg;
        afr[ks][0] = f2tf32(W2[f0 * 64 + c0]);
        afr[ks][1] = f2tf32(W2[f1 * 64 + c0]);
        afr[ks][2] = f2tf32(W2[f0 * 64 + c0 + 4]);
        afr[ks][3] = f2tf32(W2[f1 * 64 + c0 + 4]);
    }

    const float* slc = slices + (size_t)bs * Psz * 2;
    const float* msk = pmask  + (size_t)bs * Psz;

    // per-thread staged element: tid<256 -> xy, tid in [256,384) -> mask
    auto ldtile = [&](int tile) -> float {
        int pbase = tile * TP;
        if (tid < 256) {
            int idx = pbase * 2 + tid;
            return (idx < Psz * 2) ? slc[idx] : 0.f;
        } else if (tid < 384) {
            int gp = pbase + (tid - 256);
            return (gp < Psz) ? msk[gp] : 0.f;
        }
        return 0.f;
    };
    auto sttile = [&](int buf, float v) {
        if (tid < 256) sxy[buf][tid] = v;
        else if (tid < 384) smask[buf][tid - 256] = v;
    };

    float rm0 = 0.f, rm1 = 0.f;   // running max (valid feats >= 0; 0 matches all-masked case)
    float rld = ldtile(tile0);
    sttile(0, rld);
    int cur = 0;

    for (int tile = tile0; tile < tile1; tile++) {
        __syncthreads();   // buf[cur] visible; sh free to overwrite
        // ---- GEMM1: h = relu(W1 x + b1), store as tf32 bits (conflict-free: banks 4p+q) ----
        {
            int p = tid >> 2;
            int q = tid & 3;
            float x0 = sxy[cur][p * 2], x1 = sxy[cur][p * 2 + 1];
#pragma unroll
            for (int i = 0; i < 16; i++) {
                int k = q + 4 * i;
                float hv = fmaxf(sW1[k][0] * x0 + sW1[k][1] * x1 + sb1[k], 0.f);
                sh[p * HSTR + k] = __uint_as_float(f2tf32(hv));
            }
        }
        // prefetch next tile while GEMM1/mma run
        if (tile + 1 < tile1) rld = ldtile(tile + 1);
        __syncthreads();   // sh visible
        // ---- GEMM2 via tf32 mma ----
        float acc[8][4];
#pragma unroll
        for (int nt = 0; nt < 8; nt++) { acc[nt][0] = acc[nt][1] = acc[nt][2] = acc[nt][3] = 0.f; }
#pragma unroll
        for (int ks = 0; ks < 8; ks++) {
#pragma unroll
            for (int nt = 0; nt < 8; nt++) {
                int p = pjj * 64 + nt * 8 + g;                 // B col = point
                unsigned bb0 = __float_as_uint(sh[p * HSTR + ks * 8 + tg]);
                unsigned bb1 = __float_as_uint(sh[p * HSTR + ks * 8 + tg + 4]);
                mma_tf32(acc[nt], afr[ks], bb0, bb1);
            }
        }
        // ---- epilogue: bias + relu + mask + running max ----
#pragma unroll
        for (int nt = 0; nt < 8; nt++) {
            int p0 = pjj * 64 + nt * 8 + tg * 2;
            float m0 = smask[cur][p0], m1 = smask[cur][p0 + 1];
            float v;
            v = fmaxf(acc[nt][0] + b2f0, 0.f); if (m0 > 0.f) rm0 = fmaxf(rm0, v);
            v = fmaxf(acc[nt][1] + b2f0, 0.f); if (m1 > 0.f) rm0 = fmaxf(rm0, v);
            v = fmaxf(acc[nt][2] + b2f1, 0.f); if (m0 > 0.f) rm1 = fmaxf(rm1, v);
            v = fmaxf(acc[nt][3] + b2f1, 0.f); if (m1 > 0.f) rm1 = fmaxf(rm1, v);
        }
        // commit prefetched tile to the other buffer (no race: different buffer)
        if (tile + 1 < tile1) sttile(cur ^ 1, rld);
        cur ^= 1;
    }

    // reduce over the 4 point-column lanes sharing the same feature rows
    rm0 = fmaxf(rm0, __shfl_xor_sync(0xffffffffu, rm0, 1));
    rm0 = fmaxf(rm0, __shfl_xor_sync(0xffffffffu, rm0, 2));
    rm1 = fmaxf(rm1, __shfl_xor_sync(0xffffffffu, rm1, 1));
    rm1 = fmaxf(rm1, __shfl_xor_sync(0xffffffffu, rm1, 2));
    if (tg == 0) {   // nonneg floats: int-compare == float-compare
        atomicMax((int*)&smax[f0], __float_as_int(rm0));
        atomicMax((int*)&smax[f1], __float_as_int(rm1));
    }
    __syncthreads();
    if (tid < Ff) g_emb4[slice][bs * Ff + tid] = smax[tid];   // plain store, per-slice slot
}

// ---------------- kernel B1: xg = emb(_rev) @ Wi^T + bi + bh -----------------------
__global__ void xg_kernel(
    const float* __restrict__ Wi_f, const float* __restrict__ bi_f, const float* __restrict__ bh_f,
    const float* __restrict__ Wi_b, const float* __restrict__ bi_b, const float* __restrict__ bh_b)
{
    __shared__ __align__(16) float se[Ff];
    const int dir = blockIdx.x / (Bsz * Ssz);
    const int bs  = blockIdx.x % (Bsz * Ssz);
    const int b = bs / Ssz, t = bs % Ssz;
    const int src = dir ? (Ssz - 1 - t) : t;
    const int tid = threadIdx.x;  // 128
    {
        int idx = (b * Ssz + src) * Ff + tid;
        float e0 = g_emb4[0][idx], e1 = g_emb4[1][idx];
        float e2 = g_emb4[2][idx], e3 = g_emb4[3][idx];
        se[tid] = fmaxf(fmaxf(e0, e1), fmaxf(e2, e3));
    }
    __syncthreads();
    const float* Wi = dir ? Wi_b : Wi_f;
    const float* bi = dir ? bi_b : bi_f;
    const float* bh = dir ? bh_b : bh_f;
    const float4* se4 = (const float4*)se;
#pragma unroll
    for (int q = 0; q < 4; q++) {
        int j = q * 128 + tid;
        const float4* w4 = (const float4*)(Wi + j * Ff);
        float acc = bi[j] + bh[j];
#pragma unroll
        for (int i = 0; i < 32; i++) {
            float4 wv = w4[i]; float4 ev = se4[i];
            acc += wv.x * ev.x + wv.y * ev.y + wv.z * ev.z + wv.w * ev.w;
        }
        g_xg[((size_t)(dir * Bsz + b) * Ssz + t) * 512 + j] = acc;
    }
}

// ---------------- kernel B2: LSTM recurrence, one block per (dir,batch) ------------
__global__ void __launch_bounds__(1024, 1) lstm_kernel(
    const float* __restrict__ Wh_f, const float* __restrict__ Wh_b)
{
    __shared__ __align__(16) float hs[Hh];
    __shared__ float gs[4 * Hh];
    const int dir = blockIdx.x >> 2;
    const int b   = blockIdx.x & 3;
    const int tid = threadIdx.x;
    const int j  = tid >> 1;   // gate row 0..511
    const int kh = tid & 1;    // K half
    const float* Wh = dir ? Wh_b : Wh_f;

    float4 wh[16];
    const float4* w4 = (const float4*)(Wh + j * Hh + kh * 64);
#pragma unroll
    for (int i = 0; i < 16; i++) wh[i] = w4[i];

    if (tid < Hh) hs[tid] = 0.f;
    float c = 0.f;
    const float* xg = g_xg + (size_t)(dir * Bsz + b) * Ssz * 512;
    __syncthreads();

    for (int t = 0; t < Ssz; t++) {
        // hoisted xg load: issue early so the dot product + shfl hide its latency
        float xgv = (kh == 0) ? __ldg(&xg[t * 512 + j]) : 0.f;
        const float4* h4 = ((const float4*)hs) + kh * 16;
        float a0 = 0.f, a1 = 0.f;
#pragma unroll
        for (int i = 0; i < 16; i += 2) {
            float4 wv = wh[i];     float4 hv = h4[i];
            a0 += wv.x * hv.x + wv.y * hv.y + wv.z * hv.z + wv.w * hv.w;
            float4 wv2 = wh[i + 1]; float4 hv2 = h4[i + 1];
            a1 += wv2.x * hv2.x + wv2.y * hv2.y + wv2.z * hv2.z + wv2.w * hv2.w;
        }
        float acc = a0 + a1;
        acc += __shfl_xor_sync(0xffffffffu, acc, 1);   // combine K halves
        if (kh == 0) gs[j] = acc + xgv;
        __syncthreads();
        if (tid < Hh) {
            float gi = gs[tid], gf = gs[Hh + tid], gg = gs[2 * Hh + tid], go = gs[3 * Hh + tid];
            float si  = 1.f / (1.f + __expf(-gi));
            float sf_ = 1.f / (1.f + __expf(-gf));
            float so  = 1.f / (1.f + __expf(-go));
            c = sf_ * c + si * tanhf(gg);
            hs[tid] = so * tanhf(c);
        }
        __syncthreads();
    }
    if (tid < Hh) g_hfin[(dir * Bsz + b) * Hh + tid] = hs[tid];
}

// ---------------- kernel C: head ---------------------------------------------------
__global__ void head_kernel(
    const float* __restrict__ W3, const float* __restrict__ b3,
    const float* __restrict__ W4, const float* __restrict__ b4,
    float* __restrict__ out)
{
    __shared__ __align__(16) float sf[2 * Hh];
    __shared__ float red[Hh];
    const int tid = threadIdx.x;  // 128
    for (int b = 0; b < Bsz; b++) {
        sf[tid]      = g_hfin[b * Hh + tid];            // h_fwd
        sf[Hh + tid] = g_hfin[(Bsz + b) * Hh + tid];    // h_bwd
        __syncthreads();
        float acc = b3[tid];
        const float4* w4 = (const float4*)(W3 + tid * 2 * Hh);
        const float4* s4 = (const float4*)sf;
#pragma unroll
        for (int i = 0; i < 64; i++) {
            float4 wv = w4[i]; float4 sv = s4[i];
            acc += wv.x * sv.x + wv.y * sv.y + wv.z * sv.z + wv.w * sv.w;
        }
        red[tid] = fmaxf(acc, 0.f) * W4[tid];
        __syncthreads();
        if (tid < 64) red[tid] += red[tid + 64];
        __syncthreads();
        if (tid < 32) {
            float v = red[tid] + red[tid + 32];
#pragma unroll
            for (int o = 16; o; o >>= 1) v += __shfl_down_sync(0xffffffffu, v, o);
            if (tid == 0) out[b] = v + b4[0];
        }
        __syncthreads();
    }
}

// ---------------- launch -----------------------------------------------------------
extern "C" void kernel_launch(void* const* d_in, const int* in_sizes, int n_in,
                              void* d_out, int out_size)
{
    const float* slices = (const float*)d_in[0];
    const float* pmask  = (const float*)d_in[1];
    const float* W1  = (const float*)d_in[2];
    const float* b1  = (const float*)d_in[3];
    const float* W2  = (const float*)d_in[4];
    const float* b2  = (const float*)d_in[5];
    const float* Wi_f = (const float*)d_in[6];
    const float* Wh_f = (const float*)d_in[7];
    const float* bi_f = (const float*)d_in[8];
    const float* bh_f = (const float*)d_in[9];
    const float* Wi_b = (const float*)d_in[10];
    const float* Wh_b = (const float*)d_in[11];
    const float* bi_b = (const float*)d_in[12];
    const float* bh_b = (const float*)d_in[13];
    const float* W3  = (const float*)d_in[14];
    const float* b3  = (const float*)d_in[15];
    const float* W4  = (const float*)d_in[16];
    const float* b4  = (const float*)d_in[17];
    float* out = (float*)d_out;

    pointnet_kernel<<<Bsz * Ssz * NSLICE, 512>>>(slices, pmask, W1, b1, W2, b2);
    xg_kernel<<<2 * Bsz * Ssz, 128>>>(Wi_f, bi_f, bh_f, Wi_b, bi_b, bh_b);
    lstm_kernel<<<8, 1024>>>(Wh_f, Wh_b);
    head_kernel<<<1, 128>>>(W3, b3, W4, b4, out);
}

// round 16
// speedup vs baseline: 1.6226x; 1.6226x over previous
#include <cuda_runtime.h>
#include <cstdint>

#define Bsz 4
#define Ssz 80
#define Psz 6500
#define Ff  128
#define Hh  128
#define TP  128
#define QSTR 20          // q-stride (floats) in sh: 16B-aligned, conflict-free phases
#define PSTR 80          // p-stride = 4*QSTR
#define NSLICE 4
#define TILES_PER_SLICE 13   // 4*13*128 = 6656 >= 6500

// ---------------- scratch (device globals; no allocations allowed) ----------------
__device__ float g_emb4[NSLICE][Bsz * Ssz * Ff];  // per-slice partial max
__device__ float g_xg[2 * Bsz * Ssz * 4 * Hh];    // (dir,b,t,512) input-gate preacts
__device__ float g_hfin[2 * Bsz * Hh];            // final hidden per (dir,b)

// ---------------- helpers ----------------
__device__ __forceinline__ unsigned f2tf32(float x) {
    unsigned r;
    asm("cvt.rna.tf32.f32 %0, %1;" : "=r"(r) : "f"(x));
    return r;
}

__device__ __forceinline__ void mma_tf32(float* c, const unsigned* a, unsigned b0, unsigned b1) {
    asm volatile(
        "mma.sync.aligned.m16n8k8.row.col.f32.tf32.tf32.f32 "
        "{%0,%1,%2,%3}, {%4,%5,%6,%7}, {%8,%9}, {%0,%1,%2,%3};"
        : "+f"(c[0]), "+f"(c[1]), "+f"(c[2]), "+f"(c[3])
        : "r"(a[0]), "r"(a[1]), "r"(a[2]), "r"(a[3]), "r"(b0), "r"(b1));
}

// ---------------- kernel A: per-point MLP + masked max-pool ------------------------
// sh layout: sh[p*PSTR + q*QSTR + i] holds h(k = q + 4i) as tf32 bits, i in [0,16).
// mma thread (g,tg) for tile-col p needs k = ks*8+tg (i=2ks) and ks*8+tg+4 (i=2ks+1):
// one contiguous 16-float run per (p,tg) -> 4x LDS.128 per nt instead of 16 scalar LDS.
__global__ void __launch_bounds__(512, 1) pointnet_kernel(
    const float* __restrict__ slices, const float* __restrict__ pmask,
    const float* __restrict__ W1, const float* __restrict__ b1,
    const float* __restrict__ W2, const float* __restrict__ b2)
{
    __shared__ float sW1[64][2];
    __shared__ float sb1[64];
    __shared__ float sxy[2][TP * 2];    // double-buffered point staging
    __shared__ float smask[2][TP];      // double-buffered mask staging
    __shared__ __align__(16) float sh[TP * PSTR];   // tf32 bit-patterns (40KB)
    __shared__ float smax[Ff];

    const int tid   = threadIdx.x;
    const int bs    = blockIdx.x >> 2;
    const int slice = blockIdx.x & 3;
    const int tile0 = slice * TILES_PER_SLICE;
    const int tile1 = tile0 + TILES_PER_SLICE;

    if (tid < 64) { sW1[tid][0] = W1[tid * 2]; sW1[tid][1] = W1[tid * 2 + 1]; sb1[tid] = b1[tid]; }
    if (tid < Ff) smax[tid] = 0.f;

    const int w    = tid >> 5;
    const int lane = tid & 31;
    const int g    = lane >> 2;   // groupID
    const int tg   = lane & 3;    // threadID in group
    const int mi   = w >> 1;      // feature tile 0..7
    const int pjj  = w & 1;       // point half within tile
    const int f0 = mi * 16 + g, f1 = f0 + 8;
    const float b2f0 = b2[f0], b2f1 = b2[f1];

    // A fragments (W2 as A operand, M=features) -- constant across all tiles
    unsigned afr[8][4];
#pragma unroll
    for (int ks = 0; ks < 8; ks++) {
        int c0 = ks * 8 + tg;
        afr[ks][0] = f2tf32(W2[f0 * 64 + c0]);
        afr[ks][1] = f2tf32(W2[f1 * 64 + c0]);
        afr[ks][2] = f2tf32(W2[f0 * 64 + c0 + 4]);
        afr[ks][3] = f2tf32(W2[f1 * 64 + c0 + 4]);
    }

    const float* slc = slices + (size_t)bs * Psz * 2;
    const float* msk = pmask  + (size_t)bs * Psz;

    // per-thread staged element: tid<256 -> xy, tid in [256,384) -> mask
    auto ldtile = [&](int tile) -> float {
        int pbase = tile * TP;
        if (tid < 256) {
            int idx = pbase * 2 + tid;
            return (idx < Psz * 2) ? slc[idx] : 0.f;
        } else if (tid < 384) {
            int gp = pbase + (tid - 256);
            return (gp < Psz) ? msk[gp] : 0.f;
        }
        return 0.f;
    };
    auto sttile = [&](int buf, float v) {
        if (tid < 256) sxy[buf][tid] = v;
        else if (tid < 384) smask[buf][tid - 256] = v;
    };

    float rm0 = 0.f, rm1 = 0.f;   // running max (valid feats >= 0; 0 matches all-masked case)
    float rld = ldtile(tile0);
    sttile(0, rld);
    int cur = 0;

    for (int tile = tile0; tile < tile1; tile++) {
        __syncthreads();   // buf[cur] visible; sh free to overwrite
        // ---- GEMM1: h = relu(W1 x + b1) -> sh[p][q][i], k = q+4i, 4x STS.128 ----
        {
            int p = tid >> 2;
            int q = tid & 3;
            float x0 = sxy[cur][p * 2], x1 = sxy[cur][p * 2 + 1];
            float* dst = &sh[p * PSTR + q * QSTR];
#pragma unroll
            for (int c = 0; c < 4; c++) {
                float4 hv4;
                float* hp = (float*)&hv4;
#pragma unroll
                for (int j = 0; j < 4; j++) {
                    int k = q + 16 * c + 4 * j;   // i = 4c+j
                    float hv = fmaxf(sW1[k][0] * x0 + sW1[k][1] * x1 + sb1[k], 0.f);
                    hp[j] = __uint_as_float(f2tf32(hv));
                }
                *(float4*)(dst + 4 * c) = hv4;
            }
        }
        // prefetch next tile while GEMM1/mma run
        if (tile + 1 < tile1) rld = ldtile(tile + 1);
        __syncthreads();   // sh visible
        // ---- GEMM2 via tf32 mma: per nt, 4x LDS.128 then 8 mmas ----
        float acc[8][4];
#pragma unroll
        for (int nt = 0; nt < 8; nt++) { acc[nt][0] = acc[nt][1] = acc[nt][2] = acc[nt][3] = 0.f; }
#pragma unroll
        for (int nt = 0; nt < 8; nt++) {
            int p = pjj * 64 + nt * 8 + g;                 // B col = point
            const float4* bp = (const float4*)&sh[p * PSTR + tg * QSTR];
            float4 bv0 = bp[0], bv1 = bp[1], bv2 = bp[2], bv3 = bp[3];
            unsigned bq[16];
            *(float4*)&bq[0]  = bv0;
            *(float4*)&bq[4]  = bv1;
            *(float4*)&bq[8]  = bv2;
            *(float4*)&bq[12] = bv3;
#pragma unroll
            for (int ks = 0; ks < 8; ks++) {
                mma_tf32(acc[nt], afr[ks], bq[2 * ks], bq[2 * ks + 1]);
            }
        }
        // ---- epilogue: bias + relu + mask + running max ----
#pragma unroll
        for (int nt = 0; nt < 8; nt++) {
            int p0 = pjj * 64 + nt * 8 + tg * 2;
            float m0 = smask[cur][p0], m1 = smask[cur][p0 + 1];
            float v;
            v = fmaxf(acc[nt][0] + b2f0, 0.f); if (m0 > 0.f) rm0 = fmaxf(rm0, v);
            v = fmaxf(acc[nt][1] + b2f0, 0.f); if (m1 > 0.f) rm0 = fmaxf(rm0, v);
            v = fmaxf(acc[nt][2] + b2f1, 0.f); if (m0 > 0.f) rm1 = fmaxf(rm1, v);
            v = fmaxf(acc[nt][3] + b2f1, 0.f); if (m1 > 0.f) rm1 = fmaxf(rm1, v);
        }
        // commit prefetched tile to the other buffer (no race: different buffer)
        if (tile + 1 < tile1) sttile(cur ^ 1, rld);
        cur ^= 1;
    }

    // reduce over the 4 point-column lanes sharing the same feature rows
    rm0 = fmaxf(rm0, __shfl_xor_sync(0xffffffffu, rm0, 1));
    rm0 = fmaxf(rm0, __shfl_xor_sync(0xffffffffu, rm0, 2));
    rm1 = fmaxf(rm1, __shfl_xor_sync(0xffffffffu, rm1, 1));
    rm1 = fmaxf(rm1, __shfl_xor_sync(0xffffffffu, rm1, 2));
    if (tg == 0) {   // nonneg floats: int-compare == float-compare
        atomicMax((int*)&smax[f0], __float_as_int(rm0));
        atomicMax((int*)&smax[f1], __float_as_int(rm1));
    }
    __syncthreads();
    if (tid < Ff) g_emb4[slice][bs * Ff + tid] = smax[tid];   // plain store, per-slice slot
}

// ---------------- kernel B1: xg = emb(_rev) @ Wi^T + bi + bh -----------------------
__global__ void xg_kernel(
    const float* __restrict__ Wi_f, const float* __restrict__ bi_f, const float* __restrict__ bh_f,
    const float* __restrict__ Wi_b, const float* __restrict__ bi_b, const float* __restrict__ bh_b)
{
    __shared__ __align__(16) float se[Ff];
    const int dir = blockIdx.x / (Bsz * Ssz);
    const int bs  = blockIdx.x % (Bsz * Ssz);
    const int b = bs / Ssz, t = bs % Ssz;
    const int src = dir ? (Ssz - 1 - t) : t;
    const int tid = threadIdx.x;  // 128
    {
        int idx = (b * Ssz + src) * Ff + tid;
        float e0 = g_emb4[0][idx], e1 = g_emb4[1][idx];
        float e2 = g_emb4[2][idx], e3 = g_emb4[3][idx];
        se[tid] = fmaxf(fmaxf(e0, e1), fmaxf(e2, e3));
    }
    __syncthreads();
    const float* Wi = dir ? Wi_b : Wi_f;
    const float* bi = dir ? bi_b : bi_f;
    const float* bh = dir ? bh_b : bh_f;
    const float4* se4 = (const float4*)se;
#pragma unroll
    for (int q = 0; q < 4; q++) {
        int j = q * 128 + tid;
        const float4* w4 = (const float4*)(Wi + j * Ff);
        float acc = bi[j] + bh[j];
#pragma unroll
        for (int i = 0; i < 32; i++) {
            float4 wv = w4[i]; float4 ev = se4[i];
            acc += wv.x * ev.x + wv.y * ev.y + wv.z * ev.z + wv.w * ev.w;
        }
        g_xg[((size_t)(dir * Bsz + b) * Ssz + t) * 512 + j] = acc;
    }
}

// ---------------- kernel B2: LSTM recurrence, one block per (dir,batch) ------------
__global__ void __launch_bounds__(1024, 1) lstm_kernel(
    const float* __restrict__ Wh_f, const float* __restrict__ Wh_b)
{
    __shared__ __align__(16) float hs[Hh];
    __shared__ float gs[4 * Hh];
    const int dir = blockIdx.x >> 2;
    const int b   = blockIdx.x & 3;
    const int tid = threadIdx.x;
    const int j  = tid >> 1;   // gate row 0..511
    const int kh = tid & 1;    // K half
    const float* Wh = dir ? Wh_b : Wh_f;

    float4 wh[16];
    const float4* w4 = (const float4*)(Wh + j * Hh + kh * 64);
#pragma unroll
    for (int i = 0; i < 16; i++) wh[i] = w4[i];

    if (tid < Hh) hs[tid] = 0.f;
    float c = 0.f;
    const float* xg = g_xg + (size_t)(dir * Bsz + b) * Ssz * 512;
    __syncthreads();

    for (int t = 0; t < Ssz; t++) {
        // hoisted xg load: issue early so the dot product + shfl hide its latency
        float xgv = (kh == 0) ? __ldg(&xg[t * 512 + j]) : 0.f;
        const float4* h4 = ((const float4*)hs) + kh * 16;
        float a0 = 0.f, a1 = 0.f;
#pragma unroll
        for (int i = 0; i < 16; i += 2) {
            float4 wv = wh[i];     float4 hv = h4[i];
            a0 += wv.x * hv.x + wv.y * hv.y + wv.z * hv.z + wv.w * hv.w;
            float4 wv2 = wh[i + 1]; float4 hv2 = h4[i + 1];
            a1 += wv2.x * hv2.x + wv2.y * hv2.y + wv2.z * hv2.z + wv2.w * hv2.w;
        }
        float acc = a0 + a1;
        acc += __shfl_xor_sync(0xffffffffu, acc, 1);   // combine K halves
        if (kh == 0) gs[j] = acc + xgv;
        __syncthreads();
        if (tid < Hh) {
            float gi = gs[tid], gf = gs[Hh + tid], gg = gs[2 * Hh + tid], go = gs[3 * Hh + tid];
            float si  = 1.f / (1.f + __expf(-gi));
            float sf_ = 1.f / (1.f + __expf(-gf));
            float so  = 1.f / (1.f + __expf(-go));
            c = sf_ * c + si * tanhf(gg);
            hs[tid] = so * tanhf(c);
        }
        __syncthreads();
    }
    if (tid < Hh) g_hfin[(dir * Bsz + b) * Hh + tid] = hs[tid];
}

// ---------------- kernel C: head -- one block per batch, split-row dot -------------
__global__ void head_kernel(
    const float* __restrict__ W3, const float* __restrict__ b3,
    const float* __restrict__ W4, const float* __restrict__ b4,
    float* __restrict__ out)
{
    __shared__ __align__(16) float sf[2 * Hh];
    __shared__ float part[2][Hh];
    __shared__ float red[Hh];
    const int b   = blockIdx.x;     // 0..3
    const int tid = threadIdx.x;    // 256

    if (tid < Hh)            sf[tid] = g_hfin[b * Hh + tid];                 // h_fwd
    else if (tid < 2 * Hh)   sf[tid] = g_hfin[(Bsz + b) * Hh + (tid - Hh)];  // h_bwd
    __syncthreads();

    const int r  = tid & 127;   // output row
    const int hh = tid >> 7;    // half of the 256-dot
    const float4* w4 = (const float4*)(W3 + r * 2 * Hh + hh * Hh);
    const float4* s4 = (const float4*)(sf + hh * Hh);
    float acc = 0.f;
#pragma unroll
    for (int i = 0; i < 32; i++) {
        float4 wv = w4[i]; float4 sv = s4[i];
        acc += wv.x * sv.x + wv.y * sv.y + wv.z * sv.z + wv.w * sv.w;
    }
    part[hh][r] = acc;
    __syncthreads();
    if (tid < Hh) red[tid] = fmaxf(part[0][tid] + part[1][tid] + b3[tid], 0.f) * W4[tid];
    __syncthreads();
    if (tid < 64) red[tid] += red[tid + 64];
    __syncthreads();
    if (tid < 32) {
        float v = red[tid] + red[tid + 32];
#pragma unroll
        for (int o = 16; o; o >>= 1) v += __shfl_down_sync(0xffffffffu, v, o);
        if (tid == 0) out[b] = v + b4[0];
    }
}

// ---------------- launch -----------------------------------------------------------
extern "C" void kernel_launch(void* const* d_in, const int* in_sizes, int n_in,
                              void* d_out, int out_size)
{
    const float* slices = (const float*)d_in[0];
    const float* pmask  = (const float*)d_in[1];
    const float* W1  = (const float*)d_in[2];
    const float* b1  = (const float*)d_in[3];
    const float* W2  = (const float*)d_in[4];
    const float* b2  = (const float*)d_in[5];
    const float* Wi_f = (const float*)d_in[6];
    const float* Wh_f = (const float*)d_in[7];
    const float* bi_f = (const float*)d_in[8];
    const float* bh_f = (const float*)d_in[9];
    const float* Wi_b = (const float*)d_in[10];
    const float* Wh_b = (const float*)d_in[11];
    const float* bi_b = (const float*)d_in[12];
    const float* bh_b = (const float*)d_in[13];
    const float* W3  = (const float*)d_in[14];
    const float* b3  = (const float*)d_in[15];
    const float* W4  = (const float*)d_in[16];
    const float* b4  = (const float*)d_in[17];
    float* out = (float*)d_out;

    pointnet_kernel<<<Bsz * Ssz * NSLICE, 512>>>(slices, pmask, W1, b1, W2, b2);
    xg_kernel<<<2 * Bsz * Ssz, 128>>>(Wi_f, bi_f, bh_f, Wi_b, bi_b, bh_b);
    lstm_kernel<<<8, 1024>>>(Wh_f, Wh_b);
    head_kernel<<<Bsz, 256>>>(W3, b3, W4, b4, out);
}